// round 4
// baseline (speedup 1.0000x reference)
#include <cuda_runtime.h>
#include <cuda_bf16.h>
#include <math_constants.h>

#define MAXN 20000
#define MAXE 320000
#define MAXT (MAXE + MAXN)
#define CAP  128   // max degree bucket capacity (degree ~ Poisson(16)+1; P(>50) ~ 1e-5)

// ---------------- scratch (device globals; no allocation) ----------------
__device__ float g_h1[MAXN * 256];
__device__ float g_out1[MAXN * 256];
__device__ float g_as1[MAXN * 4];
__device__ float g_ad1[MAXN * 4];
__device__ float g_h2[MAXN * 21];
__device__ float g_as2[MAXN];
__device__ float g_ad2[MAXN];
__device__ int   g_cnt[MAXN];
__device__ int   g_bkt[MAXN * CAP];

__device__ __forceinline__ float leaky(float v) {
    return v > 0.f ? v : 0.2f * v;
}

// ---------------- layer1 GEMM + alpha reductions: one block per node ----------------
// Also zeroes g_cnt[n] (runs before k_scatter in stream order).
__global__ void k_gemm1(const float* __restrict__ x, const float* __restrict__ W1,
                        const float* __restrict__ asrc, const float* __restrict__ adst,
                        int N) {
    int n = blockIdx.x;
    int c = threadIdx.x;  // 0..255
    __shared__ float xs[3];
    __shared__ float red_s[8], red_d[8];
    if (c < 3) xs[c] = x[n * 3 + c];
    if (c == 32) g_cnt[n] = 0;
    __syncthreads();
    float h = fmaf(xs[0], W1[c], fmaf(xs[1], W1[256 + c], xs[2] * W1[512 + c]));
    g_h1[n * 256 + c] = h;
    float ps = h * asrc[c];
    float pd = h * adst[c];
#pragma unroll
    for (int d = 16; d; d >>= 1) {
        ps += __shfl_xor_sync(0xFFFFFFFFu, ps, d);
        pd += __shfl_xor_sync(0xFFFFFFFFu, pd, d);
    }
    int w = c >> 5;
    if ((c & 31) == 0) { red_s[w] = ps; red_d[w] = pd; }
    __syncthreads();
    if (c < 4) {
        g_as1[n * 4 + c] = red_s[2 * c] + red_s[2 * c + 1];
        g_ad1[n * 4 + c] = red_d[2 * c] + red_d[2 * c + 1];
    }
}

// ---------------- bucket scatter: edges grouped by dst, no scan needed ----------------
__global__ void k_scatter(const int* __restrict__ ei, int E, int N) {
    int i = blockIdx.x * blockDim.x + threadIdx.x;
    if (i >= E + N) return;
    int src, dst;
    if (i < E) { src = ei[i]; dst = ei[E + i]; }
    else       { src = i - E; dst = i - E; }
    int slot = atomicAdd(&g_cnt[dst], 1);
    if (slot < CAP) g_bkt[dst * CAP + slot] = src;
}

// ---------------- layer1 aggregation: one warp per dst node ----------------
__global__ void k_agg1(const float* __restrict__ b1, int N) {
    __shared__ __align__(16) float w_s[8][CAP * 4];  // 16 KB
    __shared__ int s_src[8][CAP];                    //  4 KB
    int warp = (blockIdx.x * blockDim.x + threadIdx.x) >> 5;
    int wi = threadIdx.x >> 5;
    int lane = threadIdx.x & 31;
    if (warp >= N) return;
    int dst = warp;
    const float4 ad = *(const float4*)&g_ad1[dst * 4];
    int cnt = min(g_cnt[dst], CAP);
    const int* bp = g_bkt + dst * CAP;

    // pass 1: lane-parallel e-values in registers (<=4 edges/lane, static idx)
    float e[4][4];
    int   sr[4];
    float m[4] = {-CUDART_INF_F, -CUDART_INF_F, -CUDART_INF_F, -CUDART_INF_F};
#pragma unroll
    for (int t = 0; t < 4; t++) {
        int k = lane + 32 * t;
        if (k < cnt) {
            int src = bp[k];
            sr[t] = src;
            float4 as = *(const float4*)&g_as1[src * 4];
            e[t][0] = leaky(as.x + ad.x);
            e[t][1] = leaky(as.y + ad.y);
            e[t][2] = leaky(as.z + ad.z);
            e[t][3] = leaky(as.w + ad.w);
            m[0] = fmaxf(m[0], e[t][0]);
            m[1] = fmaxf(m[1], e[t][1]);
            m[2] = fmaxf(m[2], e[t][2]);
            m[3] = fmaxf(m[3], e[t][3]);
        }
    }
#pragma unroll
    for (int d = 16; d; d >>= 1)
#pragma unroll
        for (int h = 0; h < 4; h++)
            m[h] = fmaxf(m[h], __shfl_xor_sync(0xFFFFFFFFu, m[h], d));

    // weights + segment sums, stash (w, src) in shared
    float s[4] = {0.f, 0.f, 0.f, 0.f};
#pragma unroll
    for (int t = 0; t < 4; t++) {
        int k = lane + 32 * t;
        if (k < cnt) {
            float w0 = __expf(e[t][0] - m[0]);
            float w1 = __expf(e[t][1] - m[1]);
            float w2 = __expf(e[t][2] - m[2]);
            float w3 = __expf(e[t][3] - m[3]);
            s[0] += w0; s[1] += w1; s[2] += w2; s[3] += w3;
            *(float4*)&w_s[wi][k * 4] = make_float4(w0, w1, w2, w3);
            s_src[wi][k] = sr[t];
        }
    }
#pragma unroll
    for (int d = 16; d; d >>= 1)
#pragma unroll
        for (int h = 0; h < 4; h++)
            s[h] += __shfl_xor_sync(0xFFFFFFFFu, s[h], d);
    __syncwarp();

    // pass 2: whole warp per edge, coalesced 1KB row of h1
    float acc[8] = {0.f, 0.f, 0.f, 0.f, 0.f, 0.f, 0.f, 0.f};
    for (int k = 0; k < cnt; k++) {
        float4 wv4 = *(const float4*)&w_s[wi][k * 4];  // LDS broadcast
        int src = s_src[wi][k];
        float wv[4] = {wv4.x, wv4.y, wv4.z, wv4.w};
        const float* hp = g_h1 + src * 256;
#pragma unroll
        for (int j = 0; j < 8; j++)
            acc[j] = fmaf(wv[j >> 1], hp[lane + 32 * j], acc[j]);
    }
#pragma unroll
    for (int j = 0; j < 8; j++) {
        float v = acc[j] / (s[j >> 1] + 1e-16f) + b1[lane + 32 * j];
        g_out1[dst * 256 + lane + 32 * j] = fmaxf(v, 0.f);
    }
}

// ---------------- layer2 GEMM + alpha: 8 warps/block, warp per node ----------------
__global__ void k_gemm2(const float* __restrict__ W2, const float* __restrict__ asrc2,
                        const float* __restrict__ adst2, int N) {
    __shared__ float sW[256 * 21];
    int tid = threadIdx.x;
    for (int i = tid; i < 256 * 21; i += 256) sW[i] = W2[i];
    __syncthreads();
    int warp = tid >> 5, lane = tid & 31;
    int n = blockIdx.x * 8 + warp;
    if (n >= N) return;
    float xr[8];
#pragma unroll
    for (int j = 0; j < 8; j++) xr[j] = g_out1[n * 256 + lane + 32 * j];
    float asum = 0.f, adsum = 0.f;
    for (int o = 0; o < 21; o++) {
        float p = 0.f;
#pragma unroll
        for (int j = 0; j < 8; j++) p = fmaf(xr[j], sW[(lane + 32 * j) * 21 + o], p);
#pragma unroll
        for (int d = 16; d; d >>= 1) p += __shfl_xor_sync(0xFFFFFFFFu, p, d);
        if (lane == 0) g_h2[n * 21 + o] = p;
        asum = fmaf(p, asrc2[o], asum);
        adsum = fmaf(p, adst2[o], adsum);
    }
    if (lane == 0) { g_as2[n] = asum; g_ad2[n] = adsum; }
}

// ---------------- layer2 aggregation + final row softmax: warp per node ----------------
__global__ void k_agg2(const float* __restrict__ b2, float* __restrict__ out, int N) {
    __shared__ float w_s[8][CAP];
    __shared__ int s_src[8][CAP];
    int warp = (blockIdx.x * blockDim.x + threadIdx.x) >> 5;
    int wi = threadIdx.x >> 5;
    int lane = threadIdx.x & 31;
    if (warp >= N) return;
    int dst = warp;
    float ad = g_ad2[dst];
    int cnt = min(g_cnt[dst], CAP);
    const int* bp = g_bkt + dst * CAP;

    float e[4];
    int sr[4];
    float m = -CUDART_INF_F;
#pragma unroll
    for (int t = 0; t < 4; t++) {
        int k = lane + 32 * t;
        if (k < cnt) {
            int src = bp[k];
            sr[t] = src;
            e[t] = leaky(g_as2[src] + ad);
            m = fmaxf(m, e[t]);
        }
    }
#pragma unroll
    for (int d = 16; d; d >>= 1) m = fmaxf(m, __shfl_xor_sync(0xFFFFFFFFu, m, d));

    float s = 0.f;
#pragma unroll
    for (int t = 0; t < 4; t++) {
        int k = lane + 32 * t;
        if (k < cnt) {
            float w = __expf(e[t] - m);
            s += w;
            w_s[wi][k] = w;
            s_src[wi][k] = sr[t];
        }
    }
#pragma unroll
    for (int d = 16; d; d >>= 1) s += __shfl_xor_sync(0xFFFFFFFFu, s, d);
    __syncwarp();

    float a = 0.f;
    for (int k = 0; k < cnt; k++) {
        float w = w_s[wi][k];
        int src = s_src[wi][k];
        if (lane < 21) a = fmaf(w, g_h2[src * 21 + lane], a);
    }
    float v = (lane < 21) ? (a / (s + 1e-16f) + b2[lane]) : -CUDART_INF_F;

    // row softmax over 21 lanes
    float rm = v;
#pragma unroll
    for (int d = 16; d; d >>= 1) rm = fmaxf(rm, __shfl_xor_sync(0xFFFFFFFFu, rm, d));
    float ex = (lane < 21) ? __expf(v - rm) : 0.f;
    float ss = ex;
#pragma unroll
    for (int d = 16; d; d >>= 1) ss += __shfl_xor_sync(0xFFFFFFFFu, ss, d);
    if (lane < 21) out[dst * 21 + lane] = ex / ss;
}

// ---------------- launch ----------------
extern "C" void kernel_launch(void* const* d_in, const int* in_sizes, int n_in,
                              void* d_out, int out_size) {
    const float* x     = (const float*)d_in[0];
    const int*   ei    = (const int*)d_in[1];
    const float* W1    = (const float*)d_in[2];
    const float* asrc1 = (const float*)d_in[3];
    const float* adst1 = (const float*)d_in[4];
    const float* b1    = (const float*)d_in[5];
    const float* W2    = (const float*)d_in[6];
    const float* asrc2 = (const float*)d_in[7];
    const float* adst2 = (const float*)d_in[8];
    const float* b2    = (const float*)d_in[9];
    float* out = (float*)d_out;

    int N = in_sizes[0] / 3;
    int E = in_sizes[1] / 2;
    int T = E + N;

    k_gemm1<<<N, 256>>>(x, W1, asrc1, adst1, N);        // also zeroes g_cnt
    k_scatter<<<(T + 255) / 256, 256>>>(ei, E, N);
    k_agg1<<<(N + 7) / 8, 256>>>(b1, N);
    k_gemm2<<<(N + 7) / 8, 256>>>(W2, asrc2, adst2, N);
    k_agg2<<<(N + 7) / 8, 256>>>(b2, out, N);
}

// round 8
// speedup vs baseline: 1.6285x; 1.6285x over previous
#include <cuda_runtime.h>
#include <cuda_bf16.h>
#include <math_constants.h>

#define MAXN 20000
#define MAXE 320000
#define MAXT (MAXE + MAXN)
#define CAP  128   // max degree bucket capacity (degree ~ Poisson(16)+1; P(>50) ~ 1e-5)

// ---------------- scratch (device globals; no allocation) ----------------
__device__ float g_h1[MAXN * 256];
__device__ float g_out1[MAXN * 256];
__device__ float g_as1[MAXN * 4];
__device__ float g_ad1[MAXN * 4];
__device__ float g_h2[MAXN * 21];
__device__ float g_as2[MAXN];
__device__ float g_ad2[MAXN];
__device__ int   g_cnt[MAXN];
__device__ int   g_bkt[MAXN * CAP];

__device__ __forceinline__ float leaky(float v) {
    return v > 0.f ? v : 0.2f * v;
}

// ---------------- layer1 GEMM + alpha reductions: one block per node ----------------
// Also zeroes g_cnt[n] (runs before k_scatter in stream order).
__global__ void k_gemm1(const float* __restrict__ x, const float* __restrict__ W1,
                        const float* __restrict__ asrc, const float* __restrict__ adst,
                        int N) {
    int n = blockIdx.x;
    int c = threadIdx.x;  // 0..255
    __shared__ float xs[3];
    __shared__ float red_s[8], red_d[8];
    if (c < 3) xs[c] = x[n * 3 + c];
    if (c == 32) g_cnt[n] = 0;
    __syncthreads();
    float h = fmaf(xs[0], W1[c], fmaf(xs[1], W1[256 + c], xs[2] * W1[512 + c]));
    g_h1[n * 256 + c] = h;
    float ps = h * asrc[c];
    float pd = h * adst[c];
#pragma unroll
    for (int d = 16; d; d >>= 1) {
        ps += __shfl_xor_sync(0xFFFFFFFFu, ps, d);
        pd += __shfl_xor_sync(0xFFFFFFFFu, pd, d);
    }
    int w = c >> 5;
    if ((c & 31) == 0) { red_s[w] = ps; red_d[w] = pd; }
    __syncthreads();
    if (c < 4) {
        g_as1[n * 4 + c] = red_s[2 * c] + red_s[2 * c + 1];
        g_ad1[n * 4 + c] = red_d[2 * c] + red_d[2 * c + 1];
    }
}

// ---------------- bucket scatter: edges grouped by dst, no scan needed ----------------
__global__ void k_scatter(const int* __restrict__ ei, int E, int N) {
    int i = blockIdx.x * blockDim.x + threadIdx.x;
    if (i >= E + N) return;
    int src, dst;
    if (i < E) { src = ei[i]; dst = ei[E + i]; }
    else       { src = i - E; dst = i - E; }
    int slot = atomicAdd(&g_cnt[dst], 1);
    if (slot < CAP) g_bkt[dst * CAP + slot] = src;
}

// ---------------- layer1 aggregation: one warp per dst node ----------------
__global__ void k_agg1(const float* __restrict__ b1, int N) {
    __shared__ __align__(16) float w_s[8][CAP * 4];  // 16 KB
    __shared__ int s_src[8][CAP];                    //  4 KB
    int warp = (blockIdx.x * blockDim.x + threadIdx.x) >> 5;
    int wi = threadIdx.x >> 5;
    int lane = threadIdx.x & 31;
    if (warp >= N) return;
    int dst = warp;
    const float4 ad = *(const float4*)&g_ad1[dst * 4];
    int cnt = min(g_cnt[dst], CAP);
    const int* bp = g_bkt + dst * CAP;

    // pass 1: lane-parallel e-values in registers (<=4 edges/lane, static idx)
    float e[4][4];
    int   sr[4];
    float m[4] = {-CUDART_INF_F, -CUDART_INF_F, -CUDART_INF_F, -CUDART_INF_F};
#pragma unroll
    for (int t = 0; t < 4; t++) {
        int k = lane + 32 * t;
        if (k < cnt) {
            int src = bp[k];
            sr[t] = src;
            float4 as = *(const float4*)&g_as1[src * 4];
            e[t][0] = leaky(as.x + ad.x);
            e[t][1] = leaky(as.y + ad.y);
            e[t][2] = leaky(as.z + ad.z);
            e[t][3] = leaky(as.w + ad.w);
            m[0] = fmaxf(m[0], e[t][0]);
            m[1] = fmaxf(m[1], e[t][1]);
            m[2] = fmaxf(m[2], e[t][2]);
            m[3] = fmaxf(m[3], e[t][3]);
        }
    }
#pragma unroll
    for (int d = 16; d; d >>= 1)
#pragma unroll
        for (int h = 0; h < 4; h++)
            m[h] = fmaxf(m[h], __shfl_xor_sync(0xFFFFFFFFu, m[h], d));

    // weights + segment sums, stash (w, src) in shared
    float s[4] = {0.f, 0.f, 0.f, 0.f};
#pragma unroll
    for (int t = 0; t < 4; t++) {
        int k = lane + 32 * t;
        if (k < cnt) {
            float w0 = __expf(e[t][0] - m[0]);
            float w1 = __expf(e[t][1] - m[1]);
            float w2 = __expf(e[t][2] - m[2]);
            float w3 = __expf(e[t][3] - m[3]);
            s[0] += w0; s[1] += w1; s[2] += w2; s[3] += w3;
            *(float4*)&w_s[wi][k * 4] = make_float4(w0, w1, w2, w3);
            s_src[wi][k] = sr[t];
        }
    }
#pragma unroll
    for (int d = 16; d; d >>= 1)
#pragma unroll
        for (int h = 0; h < 4; h++)
            s[h] += __shfl_xor_sync(0xFFFFFFFFu, s[h], d);
    __syncwarp();

    // pass 2: whole warp per edge, coalesced 1KB row of h1
    float acc[8] = {0.f, 0.f, 0.f, 0.f, 0.f, 0.f, 0.f, 0.f};
    for (int k = 0; k < cnt; k++) {
        float4 wv4 = *(const float4*)&w_s[wi][k * 4];  // LDS broadcast
        int src = s_src[wi][k];
        float wv[4] = {wv4.x, wv4.y, wv4.z, wv4.w};
        const float* hp = g_h1 + src * 256;
#pragma unroll
        for (int j = 0; j < 8; j++)
            acc[j] = fmaf(wv[j >> 1], hp[lane + 32 * j], acc[j]);
    }
#pragma unroll
    for (int j = 0; j < 8; j++) {
        float v = acc[j] / (s[j >> 1] + 1e-16f) + b1[lane + 32 * j];
        g_out1[dst * 256 + lane + 32 * j] = fmaxf(v, 0.f);
    }
}

// ---------------- layer2 GEMM: register-blocked tiles, no warp reductions ----------------
// Block = 128 threads, tile = 64 nodes x 24 outs (21 padded to 24).
// Thread (n_part = t&31, og = t>>5) owns 2 nodes x 6 outs in registers.
// K staged in 32-wide smem chunks; per 4-k step: 2+6 float4 LDS feed 48 FMAs.
#define TM2 64
#define KC2 32
#define XPAD (KC2 + 4)   // 36 floats/row: conflict-free strided float4 LDS
__global__ void k_gemm2(const float* __restrict__ W2, const float* __restrict__ asrc2,
                        const float* __restrict__ adst2, int N) {
    __shared__ __align__(16) float xs[TM2][XPAD];   // 9.2 KB
    __shared__ __align__(16) float wt[24][XPAD];    // 3.5 KB (W2 chunk, transposed)
    __shared__ float sa[4][TM2], sd[4][TM2];        // 2 KB

    int t = threadIdx.x;          // 0..127
    int n_part = t & 31;
    int og = t >> 5;              // 0..3 -> outputs og*6 .. og*6+5
    int n0 = blockIdx.x * TM2;

    float acc[2][6];
#pragma unroll
    for (int i = 0; i < 2; i++)
#pragma unroll
        for (int j = 0; j < 6; j++) acc[i][j] = 0.f;

    for (int k0 = 0; k0 < 256; k0 += KC2) {
        __syncthreads();
        // load x tile: 64 rows x 32 floats = 512 float4, 4 per thread, coalesced
#pragma unroll
        for (int i2 = 0; i2 < 4; i2++) {
            int idx = t + 128 * i2;
            int r = idx >> 3, c4 = idx & 7;
            int n = n0 + r;
            float4 v = make_float4(0.f, 0.f, 0.f, 0.f);
            if (n < N) v = *(const float4*)&g_out1[n * 256 + k0 + c4 * 4];
            *(float4*)&xs[r][c4 * 4] = v;
        }
        // load + transpose W2 chunk [32 k][21 o] -> wt[o][k]; zero pad rows 21..23
        for (int idx = t; idx < KC2 * 21; idx += 128) {
            int kk = idx / 21, o = idx % 21;
            wt[o][kk] = W2[(k0 + kk) * 21 + o];
        }
        if (t < 96) wt[21 + (t >> 5)][t & 31] = 0.f;
        __syncthreads();

#pragma unroll
        for (int kk = 0; kk < KC2; kk += 4) {
            float4 xv[2], wv[6];
#pragma unroll
            for (int i = 0; i < 2; i++)
                xv[i] = *(const float4*)&xs[n_part + 32 * i][kk];
#pragma unroll
            for (int j = 0; j < 6; j++)
                wv[j] = *(const float4*)&wt[og * 6 + j][kk];   // warp-broadcast
#pragma unroll
            for (int i = 0; i < 2; i++)
#pragma unroll
                for (int j = 0; j < 6; j++) {
                    acc[i][j] = fmaf(xv[i].x, wv[j].x, acc[i][j]);
                    acc[i][j] = fmaf(xv[i].y, wv[j].y, acc[i][j]);
                    acc[i][j] = fmaf(xv[i].z, wv[j].z, acc[i][j]);
                    acc[i][j] = fmaf(xv[i].w, wv[j].w, acc[i][j]);
                }
        }
    }

    // epilogue: write h2 + per-node alpha partials (no shuffles)
    float pa[2] = {0.f, 0.f}, pd[2] = {0.f, 0.f};
#pragma unroll
    for (int j = 0; j < 6; j++) {
        int o = og * 6 + j;
        if (o < 21) {
            float a_s = asrc2[o], a_d = adst2[o];
#pragma unroll
            for (int i = 0; i < 2; i++) {
                int n = n0 + n_part + 32 * i;
                if (n < N) g_h2[n * 21 + o] = acc[i][j];
                pa[i] = fmaf(acc[i][j], a_s, pa[i]);
                pd[i] = fmaf(acc[i][j], a_d, pd[i]);
            }
        }
    }
#pragma unroll
    for (int i = 0; i < 2; i++) {
        sa[og][n_part + 32 * i] = pa[i];
        sd[og][n_part + 32 * i] = pd[i];
    }
    __syncthreads();
    if (og == 0) {
#pragma unroll
        for (int i = 0; i < 2; i++) {
            int nl = n_part + 32 * i;
            int n = n0 + nl;
            if (n < N) {
                g_as2[n] = sa[0][nl] + sa[1][nl] + sa[2][nl] + sa[3][nl];
                g_ad2[n] = sd[0][nl] + sd[1][nl] + sd[2][nl] + sd[3][nl];
            }
        }
    }
}

// ---------------- layer2 aggregation + final row softmax: warp per node ----------------
__global__ void k_agg2(const float* __restrict__ b2, float* __restrict__ out, int N) {
    __shared__ float w_s[8][CAP];
    __shared__ int s_src[8][CAP];
    int warp = (blockIdx.x * blockDim.x + threadIdx.x) >> 5;
    int wi = threadIdx.x >> 5;
    int lane = threadIdx.x & 31;
    if (warp >= N) return;
    int dst = warp;
    float ad = g_ad2[dst];
    int cnt = min(g_cnt[dst], CAP);
    const int* bp = g_bkt + dst * CAP;

    float e[4];
    int sr[4];
    float m = -CUDART_INF_F;
#pragma unroll
    for (int t = 0; t < 4; t++) {
        int k = lane + 32 * t;
        if (k < cnt) {
            int src = bp[k];
            sr[t] = src;
            e[t] = leaky(g_as2[src] + ad);
            m = fmaxf(m, e[t]);
        }
    }
#pragma unroll
    for (int d = 16; d; d >>= 1) m = fmaxf(m, __shfl_xor_sync(0xFFFFFFFFu, m, d));

    float s = 0.f;
#pragma unroll
    for (int t = 0; t < 4; t++) {
        int k = lane + 32 * t;
        if (k < cnt) {
            float w = __expf(e[t] - m);
            s += w;
            w_s[wi][k] = w;
            s_src[wi][k] = sr[t];
        }
    }
#pragma unroll
    for (int d = 16; d; d >>= 1) s += __shfl_xor_sync(0xFFFFFFFFu, s, d);
    __syncwarp();

    float a = 0.f;
    for (int k = 0; k < cnt; k++) {
        float w = w_s[wi][k];
        int src = s_src[wi][k];
        if (lane < 21) a = fmaf(w, g_h2[src * 21 + lane], a);
    }
    float v = (lane < 21) ? (a / (s + 1e-16f) + b2[lane]) : -CUDART_INF_F;

    // row softmax over 21 lanes
    float rm = v;
#pragma unroll
    for (int d = 16; d; d >>= 1) rm = fmaxf(rm, __shfl_xor_sync(0xFFFFFFFFu, rm, d));
    float ex = (lane < 21) ? __expf(v - rm) : 0.f;
    float ss = ex;
#pragma unroll
    for (int d = 16; d; d >>= 1) ss += __shfl_xor_sync(0xFFFFFFFFu, ss, d);
    if (lane < 21) out[dst * 21 + lane] = ex / ss;
}

// ---------------- launch ----------------
extern "C" void kernel_launch(void* const* d_in, const int* in_sizes, int n_in,
                              void* d_out, int out_size) {
    const float* x     = (const float*)d_in[0];
    const int*   ei    = (const int*)d_in[1];
    const float* W1    = (const float*)d_in[2];
    const float* asrc1 = (const float*)d_in[3];
    const float* adst1 = (const float*)d_in[4];
    const float* b1    = (const float*)d_in[5];
    const float* W2    = (const float*)d_in[6];
    const float* asrc2 = (const float*)d_in[7];
    const float* adst2 = (const float*)d_in[8];
    const float* b2    = (const float*)d_in[9];
    float* out = (float*)d_out;

    int N = in_sizes[0] / 3;
    int E = in_sizes[1] / 2;
    int T = E + N;

    k_gemm1<<<N, 256>>>(x, W1, asrc1, adst1, N);        // also zeroes g_cnt
    k_scatter<<<(T + 255) / 256, 256>>>(ei, E, N);
    k_agg1<<<(N + 7) / 8, 256>>>(b1, N);
    k_gemm2<<<(N + TM2 - 1) / TM2, 128>>>(W2, asrc2, adst2, N);
    k_agg2<<<(N + 7) / 8, 256>>>(b2, out, N);
}

// round 10
// speedup vs baseline: 1.6974x; 1.0423x over previous
#include <cuda_runtime.h>
#include <cuda_fp16.h>
#include <math_constants.h>

#define MAXN 20000
#define MAXE 320000
#define CAP  128   // max degree bucket capacity (degree ~ Poisson(16)+1; P(>50) ~ 1e-5)

// ---------------- scratch (device globals; no allocation) ----------------
__device__ __half2 g_h1h[MAXN * 128];   // h1 in half2: index p holds channels 2p,2p+1
__device__ float g_as1[MAXN * 4];
__device__ float g_ad1[MAXN * 4];
__device__ float g_h2[MAXN * 21];
__device__ float g_as2[MAXN];
__device__ float g_ad2[MAXN];
__device__ int   g_cnt[MAXN];
__device__ int   g_bkt[MAXN * CAP];

__device__ __forceinline__ float leaky(float v) {
    return v > 0.f ? v : 0.2f * v;
}

// ---------------- layer1 GEMM + alpha reductions: 128 threads per node ----------------
// Thread t computes channels 2t, 2t+1 (both in head t>>5 == warp id, so the
// per-warp shuffle reduction lands exactly on head boundaries). Also zeroes g_cnt.
__global__ void k_gemm1(const float* __restrict__ x, const float* __restrict__ W1,
                        const float* __restrict__ asrc, const float* __restrict__ adst,
                        int N) {
    int n = blockIdx.x;
    int t = threadIdx.x;  // 0..127
    __shared__ float xs[3];
    if (t < 3) xs[t] = x[n * 3 + t];
    if (t == 4) g_cnt[n] = 0;
    __syncthreads();
    int c0 = 2 * t, c1 = 2 * t + 1;
    float h0 = fmaf(xs[0], W1[c0], fmaf(xs[1], W1[256 + c0], xs[2] * W1[512 + c0]));
    float h1v = fmaf(xs[0], W1[c1], fmaf(xs[1], W1[256 + c1], xs[2] * W1[512 + c1]));
    g_h1h[n * 128 + t] = __floats2half2_rn(h0, h1v);
    float ps = fmaf(h0, asrc[c0], h1v * asrc[c1]);
    float pd = fmaf(h0, adst[c0], h1v * adst[c1]);
#pragma unroll
    for (int d = 16; d; d >>= 1) {
        ps += __shfl_xor_sync(0xFFFFFFFFu, ps, d);
        pd += __shfl_xor_sync(0xFFFFFFFFu, pd, d);
    }
    if ((t & 31) == 0) {
        g_as1[n * 4 + (t >> 5)] = ps;
        g_ad1[n * 4 + (t >> 5)] = pd;
    }
}

// ---------------- bucket scatter: edges grouped by dst, no scan needed ----------------
__global__ void k_scatter(const int* __restrict__ ei, int E, int N) {
    int i = blockIdx.x * blockDim.x + threadIdx.x;
    if (i >= E + N) return;
    int src, dst;
    if (i < E) { src = ei[i]; dst = ei[E + i]; }
    else       { src = i - E; dst = i - E; }
    int slot = atomicAdd(&g_cnt[dst], 1);
    if (slot < CAP) g_bkt[dst * CAP + slot] = src;
}

// ---------------- layer1 aggregation FUSED with layer2 GEMM: one warp per dst ----------------
// After the softmax-weighted aggregation, the warp holds the full 256-float out1
// row in registers; the 256x21 W2 projection + alpha2 reductions happen in-register
// (g_out1 round trip and the k_gemm2 kernel are eliminated).
__global__ void k_agg1(const float* __restrict__ b1, const float* __restrict__ W2,
                       const float* __restrict__ asrc2, const float* __restrict__ adst2,
                       int N) {
    __shared__ __align__(16) float W2t[21 * 256];    // [o][c] transposed, 21 KB
    __shared__ __align__(16) float w_s[8][CAP * 4];  // 16 KB
    __shared__ int s_src[8][CAP];                    //  4 KB
    __shared__ float s_a2[21], s_d2[21];

    int t = threadIdx.x;
    // cooperative load + transpose of W2: W2t[o*256+c] = W2[c*21+o]
    for (int idx = t; idx < 21 * 256; idx += 256)
        W2t[idx] = W2[(idx & 255) * 21 + (idx >> 8)];
    if (t < 21) { s_a2[t] = asrc2[t]; s_d2[t] = adst2[t]; }
    __syncthreads();

    int warp = (blockIdx.x * blockDim.x + t) >> 5;
    int wi = t >> 5;
    int lane = t & 31;
    if (warp >= N) return;
    int dst = warp;
    const float4 ad = *(const float4*)&g_ad1[dst * 4];
    int cnt = min(g_cnt[dst], CAP);
    const int* bp = g_bkt + dst * CAP;

    // pass 1: lane-parallel e-values in registers (<=4 edges/lane)
    float e[4][4];
    int   sr[4];
    float m[4] = {-CUDART_INF_F, -CUDART_INF_F, -CUDART_INF_F, -CUDART_INF_F};
#pragma unroll
    for (int tt = 0; tt < 4; tt++) {
        int k = lane + 32 * tt;
        if (k < cnt) {
            int src = bp[k];
            sr[tt] = src;
            float4 as = *(const float4*)&g_as1[src * 4];
            e[tt][0] = leaky(as.x + ad.x);
            e[tt][1] = leaky(as.y + ad.y);
            e[tt][2] = leaky(as.z + ad.z);
            e[tt][3] = leaky(as.w + ad.w);
            m[0] = fmaxf(m[0], e[tt][0]);
            m[1] = fmaxf(m[1], e[tt][1]);
            m[2] = fmaxf(m[2], e[tt][2]);
            m[3] = fmaxf(m[3], e[tt][3]);
        }
    }
#pragma unroll
    for (int d = 16; d; d >>= 1)
#pragma unroll
        for (int h = 0; h < 4; h++)
            m[h] = fmaxf(m[h], __shfl_xor_sync(0xFFFFFFFFu, m[h], d));

    // weights + segment sums, stash (w, src) in shared
    float s[4] = {0.f, 0.f, 0.f, 0.f};
#pragma unroll
    for (int tt = 0; tt < 4; tt++) {
        int k = lane + 32 * tt;
        if (k < cnt) {
            float w0 = __expf(e[tt][0] - m[0]);
            float w1 = __expf(e[tt][1] - m[1]);
            float w2 = __expf(e[tt][2] - m[2]);
            float w3 = __expf(e[tt][3] - m[3]);
            s[0] += w0; s[1] += w1; s[2] += w2; s[3] += w3;
            *(float4*)&w_s[wi][k * 4] = make_float4(w0, w1, w2, w3);
            s_src[wi][k] = sr[tt];
        }
    }
#pragma unroll
    for (int d = 16; d; d >>= 1)
#pragma unroll
        for (int h = 0; h < 4; h++)
            s[h] += __shfl_xor_sync(0xFFFFFFFFu, s[h], d);
    __syncwarp();

    // pass 2: whole warp per edge, coalesced 512B half2 row of h1.
    // half2 index p = lane+32*jj -> channels 2p,2p+1, head = jj exactly.
    float2 acc2[4];
#pragma unroll
    for (int jj = 0; jj < 4; jj++) acc2[jj] = make_float2(0.f, 0.f);
    for (int k = 0; k < cnt; k++) {
        float4 wv4 = *(const float4*)&w_s[wi][k * 4];  // LDS broadcast
        int src = s_src[wi][k];
        float wv[4] = {wv4.x, wv4.y, wv4.z, wv4.w};
        const __half2* hp = g_h1h + src * 128;
#pragma unroll
        for (int jj = 0; jj < 4; jj++) {
            float2 f = __half22float2(hp[lane + 32 * jj]);
            acc2[jj].x = fmaf(wv[jj], f.x, acc2[jj].x);
            acc2[jj].y = fmaf(wv[jj], f.y, acc2[jj].y);
        }
    }

    // finalize out1 row in registers: /sum + b1, ReLU
    float v0[4], v1[4];
#pragma unroll
    for (int jj = 0; jj < 4; jj++) {
        int p = lane + 32 * jj;
        float inv = 1.f / (s[jj] + 1e-16f);
        float2 bb = *(const float2*)&b1[2 * p];
        v0[jj] = fmaxf(fmaf(acc2[jj].x, inv, bb.x), 0.f);
        v1[jj] = fmaxf(fmaf(acc2[jj].y, inv, bb.y), 0.f);
    }

    // fused layer2 GEMM: pacc[o] = sum_c out1[c] * W2[c][o], conflict-free LDS.64
    float pacc[21];
#pragma unroll
    for (int o = 0; o < 21; o++) pacc[o] = 0.f;
#pragma unroll
    for (int jj = 0; jj < 4; jj++) {
        int p = lane + 32 * jj;
#pragma unroll
        for (int o = 0; o < 21; o++) {
            float2 wv = *(const float2*)&W2t[o * 256 + 2 * p];
            pacc[o] = fmaf(v0[jj], wv.x, fmaf(v1[jj], wv.y, pacc[o]));
        }
    }
#pragma unroll
    for (int d = 16; d; d >>= 1)
#pragma unroll
        for (int o = 0; o < 21; o++)
            pacc[o] += __shfl_xor_sync(0xFFFFFFFFu, pacc[o], d);

    if (lane == 0) {
        float as = 0.f, adv = 0.f;
#pragma unroll
        for (int o = 0; o < 21; o++) {
            g_h2[dst * 21 + o] = pacc[o];
            as  = fmaf(pacc[o], s_a2[o], as);
            adv = fmaf(pacc[o], s_d2[o], adv);
        }
        g_as2[dst] = as;
        g_ad2[dst] = adv;
    }
}

// ---------------- layer2 aggregation + final row softmax: warp per node ----------------
__global__ void k_agg2(const float* __restrict__ b2, float* __restrict__ out, int N) {
    __shared__ float w_s[8][CAP];
    __shared__ int s_src[8][CAP];
    int warp = (blockIdx.x * blockDim.x + threadIdx.x) >> 5;
    int wi = threadIdx.x >> 5;
    int lane = threadIdx.x & 31;
    if (warp >= N) return;
    int dst = warp;
    float ad = g_ad2[dst];
    int cnt = min(g_cnt[dst], CAP);
    const int* bp = g_bkt + dst * CAP;

    float e[4];
    int sr[4];
    float m = -CUDART_INF_F;
#pragma unroll
    for (int t = 0; t < 4; t++) {
        int k = lane + 32 * t;
        if (k < cnt) {
            int src = bp[k];
            sr[t] = src;
            e[t] = leaky(g_as2[src] + ad);
            m = fmaxf(m, e[t]);
        }
    }
#pragma unroll
    for (int d = 16; d; d >>= 1) m = fmaxf(m, __shfl_xor_sync(0xFFFFFFFFu, m, d));

    float s = 0.f;
#pragma unroll
    for (int t = 0; t < 4; t++) {
        int k = lane + 32 * t;
        if (k < cnt) {
            float w = __expf(e[t] - m);
            s += w;
            w_s[wi][k] = w;
            s_src[wi][k] = sr[t];
        }
    }
#pragma unroll
    for (int d = 16; d; d >>= 1) s += __shfl_xor_sync(0xFFFFFFFFu, s, d);
    __syncwarp();

    float a = 0.f;
    for (int k = 0; k < cnt; k++) {
        float w = w_s[wi][k];
        int src = s_src[wi][k];
        if (lane < 21) a = fmaf(w, g_h2[src * 21 + lane], a);
    }
    float v = (lane < 21) ? (a / (s + 1e-16f) + b2[lane]) : -CUDART_INF_F;

    // row softmax over 21 lanes
    float rm = v;
#pragma unroll
    for (int d = 16; d; d >>= 1) rm = fmaxf(rm, __shfl_xor_sync(0xFFFFFFFFu, rm, d));
    float ex = (lane < 21) ? __expf(v - rm) : 0.f;
    float ss = ex;
#pragma unroll
    for (int d = 16; d; d >>= 1) ss += __shfl_xor_sync(0xFFFFFFFFu, ss, d);
    if (lane < 21) out[dst * 21 + lane] = ex / ss;
}

// ---------------- launch ----------------
extern "C" void kernel_launch(void* const* d_in, const int* in_sizes, int n_in,
                              void* d_out, int out_size) {
    const float* x     = (const float*)d_in[0];
    const int*   ei    = (const int*)d_in[1];
    const float* W1    = (const float*)d_in[2];
    const float* asrc1 = (const float*)d_in[3];
    const float* adst1 = (const float*)d_in[4];
    const float* b1    = (const float*)d_in[5];
    const float* W2    = (const float*)d_in[6];
    const float* asrc2 = (const float*)d_in[7];
    const float* adst2 = (const float*)d_in[8];
    const float* b2    = (const float*)d_in[9];
    float* out = (float*)d_out;

    int N = in_sizes[0] / 3;
    int E = in_sizes[1] / 2;
    int T = E + N;

    k_gemm1<<<N, 128>>>(x, W1, asrc1, adst1, N);        // also zeroes g_cnt
    k_scatter<<<(T + 255) / 256, 256>>>(ei, E, N);
    k_agg1<<<(N + 7) / 8, 256>>>(b1, W2, asrc2, adst2, N);
    k_agg2<<<(N + 7) / 8, 256>>>(b2, out, N);
}